// round 8
// baseline (speedup 1.0000x reference)
#include <cuda_runtime.h>
#include <cstdint>

// YoloLoss: pred [B,7,7,30] f32, target [B,7,7,30] f32 -> scalar f32 loss.
// Persistent kernel, WARP-DECOUPLED double-buffered cp.async pipelines:
// each warp owns a private smem region and streams its own 32-cell slice of
// each 128-cell tile, synchronizing only with __syncwarp. No block barriers
// in the hot loop -> warps drift freely, SM load stream never drains.

#define S7 7
#define CH 30
#define CPB 128                          // 4 warps per block
#define WARPS (CPB / 32)
#define WCELLS 32                        // cells per warp per tile
#define WT_FLOATS (WCELLS * CH)          // 960 floats per tensor per warp-tile
#define WT_BYTES  (WT_FLOATS * 4)        // 3840 B
#define WBUF_FLOATS (2 * WT_FLOATS)      // pred + target = 1920 floats
#define WBUF_BYTES  (WBUF_FLOATS * 4)    // 7680 B
#define WREGION_FLOATS (2 * WBUF_FLOATS) // double buffer = 3840 floats
#define SMEM_BYTES (WARPS * WREGION_FLOATS * 4)  // 61440 B per CTA
#define NBLOCKS 444                      // 3 CTAs/SM * 148 SMs
#define MAXBLK 8192

__device__ float g_partials[MAXBLK];
__device__ unsigned int g_ticket = 0;    // returns to 0 after every launch

__device__ __forceinline__ uint32_t smem_u32(const void* p) {
    return (uint32_t)__cvta_generic_to_shared(p);
}
__device__ __forceinline__ void cp16(uint32_t dst, const void* src) {
    asm volatile("cp.async.cg.shared.global [%0], [%1], 16;\n" :: "r"(dst), "l"(src));
}
__device__ __forceinline__ void cp4(uint32_t dst, const void* src) {
    asm volatile("cp.async.ca.shared.global [%0], [%1], 4;\n" :: "r"(dst), "l"(src));
}
__device__ __forceinline__ void cp_commit() {
    asm volatile("cp.async.commit_group;\n");
}
__device__ __forceinline__ void cp_wait1() {
    asm volatile("cp.async.wait_group 1;\n" ::: "memory");
}
__device__ __forceinline__ void cp_wait0() {
    asm volatile("cp.async.wait_group 0;\n" ::: "memory");
}

struct Box { float x1, y1, x2, y2; };

__device__ __forceinline__ Box convert_box(float x, float y, float w, float h,
                                           float gi, float gj) {
    const float STEPF = 1.0f / 7.0f;
    float cx = (x + gi) * STEPF;
    float cy = (y + gj) * STEPF;
    Box b;
    b.x1 = fmaxf(cx - w * 0.5f, 0.0f);
    b.y1 = fmaxf(cy - h * 0.5f, 0.0f);
    b.x2 = fminf(cx + w * 0.5f, 1.0f);
    b.y2 = fminf(cy + h * 0.5f, 1.0f);
    return b;
}

// t = target box, p = pred box — matches reference _iou(tbox, pbox) arg order.
__device__ __forceinline__ float iou_ref(const Box& t, const Box& p) {
    float minx = fmaxf(t.x1, p.x1);
    float miny = fmaxf(t.y1, p.y1);
    float maxx = fminf(t.x2, p.x2);
    float maxy = fminf(t.y2, p.y2);
    float inter = (maxy - miny) * (maxx - minx);   // faithful: no clamp
    float uni = (p.x2 - p.x1) * (p.y2 - p.y1)
              + (t.x2 - t.x1) * (t.y2 - t.y1) - inter;
    return inter > 0.0f ? inter / (uni + 1e-5f) : 0.0f;
}

// Prefetch this warp's 32-cell slice of tile `tile` into wbuf.
__device__ __forceinline__ void prefetch_warp_tile(
    float* wbuf, const float* __restrict__ pred, const float* __restrict__ target,
    int cell0, int ncells, int lane)
{
    int nvalid = min(ncells - cell0, WCELLS);
    const char* pg = (const char*)pred + (size_t)cell0 * (CH * 4);
    const char* tg = (const char*)target + (size_t)cell0 * (CH * 4);
    uint32_t sp = smem_u32(wbuf);
    uint32_t st = sp + WT_BYTES;
    if (nvalid == WCELLS) {
        // 240 float4 per tensor, coalesced 16B cp.async. cell0 % 32 == 0 so
        // byte base = cell0*120 is a multiple of 3840 -> 16B aligned.
        #pragma unroll
        for (int i = 0; i < 8; i++) {
            int idx4 = i * 32 + lane;
            if (idx4 < WT_FLOATS / 4) {
                cp16(sp + idx4 * 16, pg + idx4 * 16);
                cp16(st + idx4 * 16, tg + idx4 * 16);
            }
        }
    } else if (nvalid > 0) {
        int nf = nvalid * CH;
        for (int idx = lane; idx < nf; idx += 32) {
            cp4(sp + idx * 4, pg + (size_t)idx * 4);
            cp4(st + idx * 4, tg + (size_t)idx * 4);
        }
    }
}

__device__ __forceinline__ float compute_warp_tile(
    const float* wbuf, int cell0, int ncells, int lane)
{
    int cellg = cell0 + lane;
    if (cellg >= ncells) return 0.0f;

    const float* p = wbuf + lane * CH;
    const float* t = wbuf + WT_FLOATS + lane * CH;

    int spatial = cellg % (S7 * S7);       // i*7 + j
    float gi = (float)(spatial / S7);      // first spatial axis -> x offset
    float gj = (float)(spatial % S7);      // second spatial axis -> y offset

    Box tb = convert_box(t[0], t[1], t[2], t[3], gi, gj);
    Box p1 = convert_box(p[0], p[1], p[2], p[3], gi, gj);
    Box p2 = convert_box(p[5], p[6], p[7], p[8], gi, gj);

    float iou1 = iou_ref(tb, p1);
    float iou2 = iou_ref(tb, p2);

    bool sel2 = (iou1 <= iou2);
    float conf_t = sel2 ? iou2 : iou1;
    float px = sel2 ? p[5] : p[0];
    float py = sel2 ? p[6] : p[1];
    float pw = sel2 ? p[7] : p[2];
    float ph = sel2 ? p[8] : p[3];
    float pconf = sel2 ? p[9] : p[4];

    float tv4 = t[4];
    float obj   = (tv4 > 0.0f)  ? 1.0f : 0.0f;
    float noobj = (tv4 == 0.0f) ? 1.0f : 0.0f;

    float dx = px - t[0], dy = py - t[1];
    float dw = pw - t[2], dh = ph - t[3];
    float xywh = dx * dx + dy * dy + dw * dw + dh * dh;

    float dcls = 0.0f;
    #pragma unroll
    for (int k = 10; k < CH; k++) {
        float d = p[k] - t[k];
        dcls += d * d;
    }

    float dco = pconf - conf_t;
    float d4 = p[4] - tv4;
    float d9 = p[9] - t[9];
    float dno = d4 * d4 + d9 * d9;

    return obj * (dco * dco) + 0.5f * noobj * dno
         + 5.0f * obj * xywh + obj * dcls;
}

extern __shared__ float dynsmem[];

__global__ __launch_bounds__(CPB) void yolo_loss_kernel(
    const float* __restrict__ pred,
    const float* __restrict__ target,
    int ncells, int ntiles, float invB, float* __restrict__ out)
{
    __shared__ float warp_part[WARPS];
    __shared__ int s_last;

    const int tid = threadIdx.x;
    const int lane = tid & 31;
    const int wid = tid >> 5;
    const int bid = blockIdx.x;
    const int stride = gridDim.x;

    // Warp-private double buffer.
    float* wreg = dynsmem + wid * WREGION_FLOATS;
    float* buf0 = wreg;
    float* buf1 = wreg + WBUF_FLOATS;

    float acc = 0.0f;

    // Prologue: prefetch this warp's slice of the first tile.
    int t = bid;
    if (t < ntiles)
        prefetch_warp_tile(buf0, pred, target, t * CPB + wid * WCELLS, ncells, lane);
    cp_commit();

    int cur = 0;
    for (; t < ntiles; t += stride) {
        int tn = t + stride;
        bool more = (tn < ntiles);
        float* nbuf = cur ? buf0 : buf1;
        float* cbuf = cur ? buf1 : buf0;
        if (more)
            prefetch_warp_tile(nbuf, pred, target, tn * CPB + wid * WCELLS, ncells, lane);
        cp_commit();
        if (more) cp_wait1(); else cp_wait0();
        __syncwarp();                    // all lanes' copies of cbuf visible
        acc += compute_warp_tile(cbuf, t * CPB + wid * WCELLS, ncells, lane);
        __syncwarp();                    // all lanes done reading before reuse
        cur ^= 1;
    }

    // Warp reduce, then one block reduce at the very end.
    #pragma unroll
    for (int o = 16; o > 0; o >>= 1)
        acc += __shfl_xor_sync(0xffffffffu, acc, o);

    if (lane == 0) warp_part[wid] = acc;
    __syncthreads();

    if (tid == 0) {
        float s = 0.0f;
        #pragma unroll
        for (int w = 0; w < WARPS; w++) s += warp_part[w];
        g_partials[bid] = s;                       // every slot written: no init needed
        __threadfence();
        unsigned int v = atomicAdd(&g_ticket, 1u);
        s_last = (v == gridDim.x - 1) ? 1 : 0;
    }
    __syncthreads();

    if (s_last) {
        int nblk = gridDim.x;
        float r = 0.0f;
        for (int i = tid; i < nblk; i += CPB)
            r += g_partials[i];
        #pragma unroll
        for (int o = 16; o > 0; o >>= 1)
            r += __shfl_xor_sync(0xffffffffu, r, o);
        if (lane == 0) warp_part[wid] = r;
        __syncthreads();
        if (tid == 0) {
            double total = 0.0;
            #pragma unroll
            for (int w = 0; w < WARPS; w++) total += (double)warp_part[w];
            out[0] = (float)(total * (double)invB);
            g_ticket = 0;                          // restore invariant for replays
        }
    }
}

extern "C" void kernel_launch(void* const* d_in, const int* in_sizes, int n_in,
                              void* d_out, int out_size) {
    const float* pred = (const float*)d_in[0];
    const float* target = (const float*)d_in[1];
    float* out = (float*)d_out;

    int ncells = in_sizes[0] / CH;                 // B * 7 * 7
    int B = ncells / (S7 * S7);
    int ntiles = (ncells + CPB - 1) / CPB;         // 6272 for B=16384

    static int attr_set = 0;
    if (!attr_set) {
        cudaFuncSetAttribute(yolo_loss_kernel,
                             cudaFuncAttributeMaxDynamicSharedMemorySize,
                             SMEM_BYTES);
        attr_set = 1;
    }

    yolo_loss_kernel<<<NBLOCKS, CPB, SMEM_BYTES>>>(
        pred, target, ncells, ntiles, 1.0f / (float)B, out);
}

// round 9
// speedup vs baseline: 1.0589x; 1.0589x over previous
#include <cuda_runtime.h>
#include <cstdint>

// YoloLoss: pred [B,7,7,30] f32, target [B,7,7,30] f32 -> scalar f32 loss.
// Persistent kernel, 3-stage TMA-bulk (cp.async.bulk -> UBLKCP) pipeline.
// Rationale: per-thread cp.async was LSU-dispatch-bound (12M ops at the ~4cyc
// accept floor). One bulk instruction moves 15360B, so the LSU drops out and
// the kernel runs at the HBM/LTS ceiling. mbarrier expect_tx completion.

#define S7 7
#define CH 30
#define CPB 128                           // threads per block == cells per tile
#define TILE_FLOATS (CPB * CH)            // 3840
#define TILE_BYTES  (TILE_FLOATS * 4)     // 15360 (16B multiple)
#define STAGE_FLOATS (2 * TILE_FLOATS)    // pred + target
#define STAGE_BYTES  (2 * TILE_BYTES)     // 30720
#define NSTAGES 3
#define SMEM_BYTES (NSTAGES * STAGE_BYTES) // 92160
#define NBLOCKS 296                       // 2 CTAs/SM * 148 SMs
#define MAXBLK 8192

__device__ float g_partials[MAXBLK];
__device__ unsigned int g_ticket = 0;     // returns to 0 after every launch

__device__ __forceinline__ uint32_t smem_u32(const void* p) {
    return (uint32_t)__cvta_generic_to_shared(p);
}
__device__ __forceinline__ void mbar_init(uint32_t mbar, uint32_t count) {
    asm volatile("mbarrier.init.shared.b64 [%0], %1;" :: "r"(mbar), "r"(count) : "memory");
}
__device__ __forceinline__ void mbar_expect_tx(uint32_t mbar, uint32_t bytes) {
    asm volatile("mbarrier.arrive.expect_tx.shared.b64 _, [%0], %1;"
                 :: "r"(mbar), "r"(bytes) : "memory");
}
__device__ __forceinline__ void mbar_wait(uint32_t mbar, uint32_t parity) {
    uint32_t done;
    asm volatile(
        "{\n\t.reg .pred p;\n\t"
        "mbarrier.try_wait.parity.acquire.cta.shared::cta.b64 p, [%1], %2;\n\t"
        "selp.b32 %0, 1, 0, p;\n\t}"
        : "=r"(done) : "r"(mbar), "r"(parity) : "memory");
    if (!done) {
        asm volatile(
            "{\n\t.reg .pred P1;\n\t"
            "W_%=:\n\t"
            "mbarrier.try_wait.parity.acquire.cta.shared::cta.b64 P1, [%0], %1, 0x989680;\n\t"
            "@P1 bra.uni D_%=;\n\t"
            "bra.uni W_%=;\n\t"
            "D_%=:\n\t}"
            :: "r"(mbar), "r"(parity) : "memory");
    }
}
__device__ __forceinline__ void tma_bulk_g2s(uint32_t dst, const void* src,
                                             uint32_t bytes, uint32_t mbar) {
    asm volatile(
        "cp.async.bulk.shared::cta.global.mbarrier::complete_tx::bytes "
        "[%0], [%1], %2, [%3];"
        :: "r"(dst), "l"(src), "r"(bytes), "r"(mbar) : "memory");
}

struct Box { float x1, y1, x2, y2; };

__device__ __forceinline__ Box convert_box(float x, float y, float w, float h,
                                           float gi, float gj) {
    const float STEPF = 1.0f / 7.0f;
    float cx = (x + gi) * STEPF;
    float cy = (y + gj) * STEPF;
    Box b;
    b.x1 = fmaxf(cx - w * 0.5f, 0.0f);
    b.y1 = fmaxf(cy - h * 0.5f, 0.0f);
    b.x2 = fminf(cx + w * 0.5f, 1.0f);
    b.y2 = fminf(cy + h * 0.5f, 1.0f);
    return b;
}

// t = target box, p = pred box — matches reference _iou(tbox, pbox) arg order.
__device__ __forceinline__ float iou_ref(const Box& t, const Box& p) {
    float minx = fmaxf(t.x1, p.x1);
    float miny = fmaxf(t.y1, p.y1);
    float maxx = fminf(t.x2, p.x2);
    float maxy = fminf(t.y2, p.y2);
    float inter = (maxy - miny) * (maxx - minx);   // faithful: no clamp
    float uni = (p.x2 - p.x1) * (p.y2 - p.y1)
              + (t.x2 - t.x1) * (t.y2 - t.y1) - inter;
    return inter > 0.0f ? inter / (uni + 1e-5f) : 0.0f;
}

// Per-cell loss. p/t point at this thread's 30 floats.
__device__ __forceinline__ float cell_loss(const float* p, const float* t, int cellg) {
    int spatial = cellg % (S7 * S7);       // i*7 + j
    float gi = (float)(spatial / S7);      // first spatial axis -> x offset
    float gj = (float)(spatial % S7);      // second spatial axis -> y offset

    Box tb = convert_box(t[0], t[1], t[2], t[3], gi, gj);
    Box p1 = convert_box(p[0], p[1], p[2], p[3], gi, gj);
    Box p2 = convert_box(p[5], p[6], p[7], p[8], gi, gj);

    float iou1 = iou_ref(tb, p1);
    float iou2 = iou_ref(tb, p2);

    bool sel2 = (iou1 <= iou2);
    float conf_t = sel2 ? iou2 : iou1;
    float px = sel2 ? p[5] : p[0];
    float py = sel2 ? p[6] : p[1];
    float pw = sel2 ? p[7] : p[2];
    float ph = sel2 ? p[8] : p[3];
    float pconf = sel2 ? p[9] : p[4];

    float tv4 = t[4];
    float obj   = (tv4 > 0.0f)  ? 1.0f : 0.0f;
    float noobj = (tv4 == 0.0f) ? 1.0f : 0.0f;

    float dx = px - t[0], dy = py - t[1];
    float dw = pw - t[2], dh = ph - t[3];
    float xywh = dx * dx + dy * dy + dw * dw + dh * dh;

    float dcls = 0.0f;
    #pragma unroll
    for (int k = 10; k < CH; k++) {
        float d = p[k] - t[k];
        dcls += d * d;
    }

    float dco = pconf - conf_t;
    float d4 = p[4] - tv4;
    float d9 = p[9] - t[9];
    float dno = d4 * d4 + d9 * d9;

    return obj * (dco * dco) + 0.5f * noobj * dno
         + 5.0f * obj * xywh + obj * dcls;
}

extern __shared__ float dynsmem[];   // NSTAGES stage buffers

__global__ __launch_bounds__(CPB) void yolo_loss_kernel(
    const float* __restrict__ pred,
    const float* __restrict__ target,
    int ncells, int tfull, float invB, float* __restrict__ out)
{
    __shared__ __align__(8) unsigned long long mbar_store[NSTAGES];
    __shared__ float warp_part[CPB / 32];
    __shared__ int s_last;

    const int tid = threadIdx.x;
    const int lane = tid & 31;
    const int wid = tid >> 5;
    const int bid = blockIdx.x;
    const int G = gridDim.x;

    const uint32_t mbar0 = smem_u32(mbar_store);
    const uint32_t sbase = smem_u32(dynsmem);

    if (tid == 0) {
        #pragma unroll
        for (int s = 0; s < NSTAGES; s++)
            mbar_init(mbar0 + s * 8, 1);
    }
    __syncthreads();   // barriers visible to all before any bulk targets them

    // Prologue: fill the pipeline.
    if (tid == 0) {
        #pragma unroll
        for (int k = 0; k < NSTAGES; k++) {
            int t = bid + k * G;
            if (t < tfull) {
                uint32_t mb = mbar0 + k * 8;
                uint32_t dst = sbase + k * STAGE_BYTES;
                mbar_expect_tx(mb, STAGE_BYTES);
                tma_bulk_g2s(dst, pred + (size_t)t * TILE_FLOATS, TILE_BYTES, mb);
                tma_bulk_g2s(dst + TILE_BYTES, target + (size_t)t * TILE_FLOATS,
                             TILE_BYTES, mb);
            }
        }
    }

    float acc = 0.0f;
    int i = 0;
    for (int t = bid; t < tfull; t += G, i++) {
        int s = i % NSTAGES;
        uint32_t parity = (uint32_t)((i / NSTAGES) & 1);
        uint32_t mb = mbar0 + s * 8;
        mbar_wait(mb, parity);

        const float* buf = dynsmem + s * STAGE_FLOATS;
        const float* p = buf + tid * CH;
        const float* tt = buf + TILE_FLOATS + tid * CH;
        acc += cell_loss(p, tt, t * CPB + tid);

        __syncthreads();               // everyone done with stage s before refill
        int tpre = t + NSTAGES * G;
        if (tpre < tfull && tid == 0) {
            uint32_t dst = sbase + s * STAGE_BYTES;
            mbar_expect_tx(mb, STAGE_BYTES);
            tma_bulk_g2s(dst, pred + (size_t)tpre * TILE_FLOATS, TILE_BYTES, mb);
            tma_bulk_g2s(dst + TILE_BYTES, target + (size_t)tpre * TILE_FLOATS,
                         TILE_BYTES, mb);
        }
    }

    // Remainder cells (ncells % CPB != 0): block 0 reads them straight from gmem.
    if (bid == 0) {
        int cellg = tfull * CPB + tid;
        if (cellg < ncells) {
            float pl[CH], tl[CH];
            const float* pg = pred + (size_t)cellg * CH;
            const float* tg = target + (size_t)cellg * CH;
            #pragma unroll
            for (int k = 0; k < CH; k++) { pl[k] = pg[k]; tl[k] = tg[k]; }
            acc += cell_loss(pl, tl, cellg);
        }
    }

    // Warp reduce, then block reduce.
    #pragma unroll
    for (int o = 16; o > 0; o >>= 1)
        acc += __shfl_xor_sync(0xffffffffu, acc, o);

    if (lane == 0) warp_part[wid] = acc;
    __syncthreads();

    if (tid == 0) {
        float ssum = 0.0f;
        #pragma unroll
        for (int w = 0; w < CPB / 32; w++) ssum += warp_part[w];
        g_partials[bid] = ssum;                    // every slot written: no init needed
        __threadfence();
        unsigned int v = atomicAdd(&g_ticket, 1u);
        s_last = (v == gridDim.x - 1) ? 1 : 0;
    }
    __syncthreads();

    if (s_last) {
        int nblk = gridDim.x;
        float r = 0.0f;
        for (int j = tid; j < nblk; j += CPB)
            r += g_partials[j];
        #pragma unroll
        for (int o = 16; o > 0; o >>= 1)
            r += __shfl_xor_sync(0xffffffffu, r, o);
        if (lane == 0) warp_part[wid] = r;
        __syncthreads();
        if (tid == 0) {
            double total = 0.0;
            #pragma unroll
            for (int w = 0; w < CPB / 32; w++) total += (double)warp_part[w];
            out[0] = (float)(total * (double)invB);
            g_ticket = 0;                          // restore invariant for replays
        }
    }
}

extern "C" void kernel_launch(void* const* d_in, const int* in_sizes, int n_in,
                              void* d_out, int out_size) {
    const float* pred = (const float*)d_in[0];
    const float* target = (const float*)d_in[1];
    float* out = (float*)d_out;

    int ncells = in_sizes[0] / CH;                 // B * 7 * 7
    int B = ncells / (S7 * S7);
    int tfull = ncells / CPB;                      // 6272 full tiles for B=16384

    static int attr_set = 0;
    if (!attr_set) {
        cudaFuncSetAttribute(yolo_loss_kernel,
                             cudaFuncAttributeMaxDynamicSharedMemorySize,
                             SMEM_BYTES);
        attr_set = 1;
    }

    yolo_loss_kernel<<<NBLOCKS, CPB, SMEM_BYTES>>>(
        pred, target, ncells, tfull, 1.0f / (float)B, out);
}